// round 15
// baseline (speedup 1.0000x reference)
#include <cuda_runtime.h>
#include <math.h>

#define BSZ 16
#define SSZ 1024
#define HSZ 256
#define G4H 1024

// ------------------------- scratch (__device__ globals) ---------------------
__device__ float g_xg[BSZ * SSZ * G4H];
__device__ float g_b0[BSZ * SSZ * HSZ];
__device__ float g_b1[BSZ * SSZ * HSZ];
__device__ float g_q [BSZ * SSZ * HSZ];
__device__ float g_k [BSZ * SSZ * HSZ];
__device__ float g_v [BSZ * SSZ * HSZ];

// no-op: pads the launch sequence so lstm_kernel sits at launch #4 (ncu slot)
__global__ void nop_a() {}

// ---------------------------------------------------------------------------
// Generic fp32 GEMM: C[M,N] = A[M,K] @ Bm[N,K]^T + bias[N] (+bias2[N]),
// optional per-row valid mask. M,N mult of 64; K mult of 16. 256 thr, 4x4 micro.
// ---------------------------------------------------------------------------
__global__ __launch_bounds__(256) void gemm_tn(
    const float* __restrict__ A, const float* __restrict__ Bm,
    const float* __restrict__ bias, const float* __restrict__ bias2,
    const int* __restrict__ lengths,
    float* __restrict__ C, int M, int N, int K)
{
    __shared__ float sA[16][68];
    __shared__ float sB[16][68];

    const int tid = threadIdx.x;
    const int tx = tid & 15;
    const int ty = tid >> 4;
    const int m0 = blockIdx.y * 64;
    const int n0 = blockIdx.x * 64;
    const int am = tid >> 2;
    const int ak = (tid & 3) * 4;

    float c[4][4];
    #pragma unroll
    for (int i = 0; i < 4; i++)
        #pragma unroll
        for (int j = 0; j < 4; j++) c[i][j] = 0.f;

    for (int k0 = 0; k0 < K; k0 += 16) {
        float4 av = *(const float4*)(A  + (size_t)(m0 + am) * K + k0 + ak);
        float4 bv = *(const float4*)(Bm + (size_t)(n0 + am) * K + k0 + ak);
        __syncthreads();
        sA[ak+0][am] = av.x; sA[ak+1][am] = av.y; sA[ak+2][am] = av.z; sA[ak+3][am] = av.w;
        sB[ak+0][am] = bv.x; sB[ak+1][am] = bv.y; sB[ak+2][am] = bv.z; sB[ak+3][am] = bv.w;
        __syncthreads();
        #pragma unroll
        for (int k = 0; k < 16; k++) {
            float4 a4 = *(const float4*)(&sA[k][ty << 2]);
            float4 b4 = *(const float4*)(&sB[k][tx << 2]);
            float ar[4] = {a4.x, a4.y, a4.z, a4.w};
            float br[4] = {b4.x, b4.y, b4.z, b4.w};
            #pragma unroll
            for (int i = 0; i < 4; i++)
                #pragma unroll
                for (int j = 0; j < 4; j++)
                    c[i][j] = fmaf(ar[i], br[j], c[i][j]);
        }
    }

    const int nn = n0 + (tx << 2);
    float bb[4];
    #pragma unroll
    for (int j = 0; j < 4; j++) {
        bb[j] = bias ? bias[nn + j] : 0.f;
        if (bias2) bb[j] += bias2[nn + j];
    }
    #pragma unroll
    for (int i = 0; i < 4; i++) {
        int rowm = m0 + (ty << 2) + i;
        float msk = 1.f;
        if (lengths) {
            int bt = rowm >> 10;
            int sq = rowm & 1023;
            msk = (sq < lengths[bt]) ? 1.f : 0.f;
        }
        float4 o;
        o.x = (c[i][0] + bb[0]) * msk;
        o.y = (c[i][1] + bb[1]) * msk;
        o.z = (c[i][2] + bb[2]) * msk;
        o.w = (c[i][3] + bb[3]) * msk;
        *(float4*)(C + (size_t)rowm * N + nn) = o;
    }
}

// ---------------------------------------------------------------------------
// LSTM recurrence (Round-7/12 configuration), run TWICE internally
// (NPASS=2) for duration measurement: L = T_total - T_round12.
// Pass 2 re-initializes all state (h, c, mbarriers) to kernel-entry
// conditions between cluster_sync fences, and rewrites hob with identical
// values — output unchanged, runtime + L.
// ---------------------------------------------------------------------------
#define NPASS 2

__device__ __forceinline__ unsigned smem_u32(const void* p) {
    return (unsigned)__cvta_generic_to_shared(p);
}
__device__ __forceinline__ void cluster_sync_() {
    asm volatile("barrier.cluster.arrive.aligned;\n\tbarrier.cluster.wait.aligned;" ::: "memory");
}
__device__ __forceinline__ unsigned mapa_(unsigned laddr, int r) {
    unsigned ra;
    asm volatile("mapa.shared::cluster.u32 %0, %1, %2;" : "=r"(ra) : "r"(laddr), "r"(r));
    return ra;
}
__device__ __forceinline__ float sig_f(float x) {
    return __fdividef(1.f, 1.f + __expf(-x));
}
__device__ __forceinline__ float tanh_f(float x) {
    return 1.f - __fdividef(2.f, __expf(2.f * x) + 1.f);
}

__global__ __cluster_dims__(8, 1, 1) __launch_bounds__(256, 1)
void lstm_kernel(const float* __restrict__ xg, const float* __restrict__ w_hh,
                 const int* __restrict__ lengths, float* __restrict__ hout)
{
    __shared__ float4 wsm[8][256];                     // 32KB weight tail
    __shared__ __align__(16) float h_s[2][256];
    __shared__ float sg[128];
    __shared__ __align__(8) unsigned long long mbar[2];

    unsigned rank;
    asm("mov.u32 %0, %%cluster_ctarank;" : "=r"(rank));
    const int batch = blockIdx.x >> 3;
    const int t  = threadIdx.x;
    const int g  = t >> 1;
    const int hh = t & 1;
    const int row = ((g >> 5) << 8) + (int)rank * 32 + (g & 31);
    const float4* wr = (const float4*)(w_hh + (size_t)row * 256 + hh * 128);

    float4 w[24];
    #pragma unroll
    for (int i = 0; i < 24; i++) w[i] = wr[i];
    #pragma unroll
    for (int j = 0; j < 8; j++) wsm[j][t] = wr[24 + j];

    // precompute remote send addresses (warp 0 only; constant across passes)
    unsigned ra0[2] = {0, 0}, ra1[2] = {0, 0}, rm0[2] = {0, 0}, rm1[2] = {0, 0};
    if (t < 32) {
        #pragma unroll
        for (int rep = 0; rep < 2; rep++) {
            int a = rep * 32 + t;
            int dst = a >> 3;
            int ch  = a & 7;
            ra0[rep] = mapa_(smem_u32(&h_s[0][(int)rank * 32 + ch * 4]), dst);
            ra1[rep] = mapa_(smem_u32(&h_s[1][(int)rank * 32 + ch * 4]), dst);
            rm0[rep] = mapa_(smem_u32(&mbar[0]), dst);
            rm1[rep] = mapa_(smem_u32(&mbar[1]), dst);
        }
    }

    const int len = lengths[batch];
    const float* xgb = xg + (size_t)batch * SSZ * G4H;
    float* hob = hout + (size_t)batch * SSZ * HSZ;

    for (int pass = 0; pass < NPASS; pass++) {
        // ---- (re)initialize state to kernel-entry conditions ----
        h_s[0][t] = 0.f;
        h_s[1][t] = 0.f;
        if (t == 0) {
            if (pass > 0) {
                asm volatile("mbarrier.inval.shared.b64 [%0];" :: "r"(smem_u32(&mbar[0])) : "memory");
                asm volatile("mbarrier.inval.shared.b64 [%0];" :: "r"(smem_u32(&mbar[1])) : "memory");
            }
            asm volatile("mbarrier.init.shared.b64 [%0], 1;" :: "r"(smem_u32(&mbar[0])) : "memory");
            asm volatile("mbarrier.init.shared.b64 [%0], 1;" :: "r"(smem_u32(&mbar[1])) : "memory");
        }
        __syncthreads();
        cluster_sync_();   // barriers init'd + h zeroed cluster-wide before traffic

        float c = 0.f;
        float xgv = (hh == 0) ? __ldg(xgb + row) : 0.f;

        for (int s = 0; s < SSZ; s++) {
            // prefetch next step's pre-gate value
            float xgn = 0.f;
            if (hh == 0 && s < SSZ - 1) xgn = __ldg(xgb + (size_t)(s + 1) * G4H + row);

            // arm the barrier that collects step-(s+1) h data (1024 tx bytes)
            if (t == 0 && s < SSZ - 1) {
                unsigned mb = smem_u32(&mbar[(s + 1) & 1]);
                asm volatile("mbarrier.arrive.expect_tx.shared.b64 _, [%0], %1;"
                             :: "r"(mb), "r"(1024u) : "memory");
            }

            // wait for h[s&1]
            if (s > 0) {
                unsigned ad = smem_u32(&mbar[s & 1]);
                unsigned par = (s & 1) ? ((unsigned)(s >> 1) & 1u)
                                       : (((unsigned)(s >> 1) + 1u) & 1u);
                asm volatile(
                    "{\n\t.reg .pred P;\n"
                    "WAITL%=:\n\t"
                    "mbarrier.try_wait.parity.acquire.cta.shared::cta.b64 P, [%0], %1, 0x989680;\n\t"
                    "@!P bra WAITL%=;\n\t}"
                    :: "r"(ad), "r"(par) : "memory");
            }

            const float4* hp = (const float4*)(&h_s[s & 1][hh * 128]);
            float a0 = 0.f, a1 = 0.f, a2 = 0.f, a3 = 0.f;
            #pragma unroll
            for (int i = 0; i < 24; i++) {
                float4 hv = hp[i];
                a0 = fmaf(w[i].x, hv.x, a0);
                a1 = fmaf(w[i].y, hv.y, a1);
                a2 = fmaf(w[i].z, hv.z, a2);
                a3 = fmaf(w[i].w, hv.w, a3);
            }
            #pragma unroll
            for (int j = 0; j < 8; j++) {
                float4 wv = wsm[j][t];
                float4 hv = hp[24 + j];
                a0 = fmaf(wv.x, hv.x, a0);
                a1 = fmaf(wv.y, hv.y, a1);
                a2 = fmaf(wv.z, hv.z, a2);
                a3 = fmaf(wv.w, hv.w, a3);
            }
            float acc = (a0 + a1) + (a2 + a3);
            acc += __shfl_xor_sync(0xffffffffu, acc, 1);   // combine k-halves
            if (hh == 0) sg[g] = acc + xgv;
            __syncthreads();   // sg ready; all warps done reading h_s[s&1]

            if (t < 32) {   // warp 0: activations + h exchange + output store
                float gi = sig_f(sg[t]);
                float gf = sig_f(sg[32 + t]);
                float go = sig_f(sg[96 + t]);
                float tg = tanh_f(sg[64 + t]);
                c = gf * c + gi * tg;
                float hn = go * tanh_f(c);

                if (s < SSZ - 1) {
                    const int np = (s + 1) & 1;
                    #pragma unroll
                    for (int rep = 0; rep < 2; rep++) {
                        int a  = rep * 32 + t;
                        int ch = a & 7;
                        unsigned ra = np ? ra1[rep] : ra0[rep];
                        unsigned rm = np ? rm1[rep] : rm0[rep];
                        unsigned vx = __float_as_uint(__shfl_sync(0xffffffffu, hn, ch * 4 + 0));
                        unsigned vy = __float_as_uint(__shfl_sync(0xffffffffu, hn, ch * 4 + 1));
                        unsigned vz = __float_as_uint(__shfl_sync(0xffffffffu, hn, ch * 4 + 2));
                        unsigned vw = __float_as_uint(__shfl_sync(0xffffffffu, hn, ch * 4 + 3));
                        asm volatile(
                            "st.async.shared::cluster.mbarrier::complete_tx::bytes.v4.b32 "
                            "[%0], {%1,%2,%3,%4}, [%5];"
                            :: "r"(ra), "r"(vx), "r"(vy), "r"(vz), "r"(vw), "r"(rm)
                            : "memory");
                    }
                }
                hob[(size_t)s * HSZ + (int)rank * 32 + t] = (s < len) ? hn : 0.f;
            }
            xgv = xgn;
        }
        cluster_sync_();   // all pass traffic drained before re-init / exit
    }
}

// ---------------------------------------------------------------------------
// Flash-style causal attention, fp32, Dh=256. BQ=BK=64, 256 threads.
// ---------------------------------------------------------------------------
#define ATTN_SMEM_BYTES ((4160 + 4160 + 4096) * 16 + 4160 * 4)  // 215296 B

__device__ __forceinline__ float hmax16(float v) {
    v = fmaxf(v, __shfl_xor_sync(0xffffffffu, v, 8));
    v = fmaxf(v, __shfl_xor_sync(0xffffffffu, v, 4));
    v = fmaxf(v, __shfl_xor_sync(0xffffffffu, v, 2));
    v = fmaxf(v, __shfl_xor_sync(0xffffffffu, v, 1));
    return v;
}
__device__ __forceinline__ float hsum16(float v) {
    v += __shfl_xor_sync(0xffffffffu, v, 8);
    v += __shfl_xor_sync(0xffffffffu, v, 4);
    v += __shfl_xor_sync(0xffffffffu, v, 2);
    v += __shfl_xor_sync(0xffffffffu, v, 1);
    return v;
}

__global__ __launch_bounds__(256) void attn_kernel(
    const float* __restrict__ Q, const float* __restrict__ K,
    const float* __restrict__ V, float* __restrict__ O)
{
    extern __shared__ float smf[];
    float4* Qt = (float4*)smf;        // [d4=64][65]
    float4* Kt = Qt + 4160;           // [d4=64][65]
    float4* Vs = Kt + 4160;           // [k=64][d4=64]
    float*  Ps = (float*)(Vs + 4096); // [64][65]

    const int b   = blockIdx.y;
    const int qb  = (int)gridDim.x - 1 - (int)blockIdx.x;
    const int tid = threadIdx.x;
    const int kf  = tid & 15;
    const int qf  = tid >> 4;

    const float4* Qg = (const float4*)(Q + ((size_t)b * SSZ + qb * 64) * HSZ);
    for (int idx = tid; idx < 4096; idx += 256)
        Qt[(idx & 63) * 65 + (idx >> 6)] = Qg[idx];

    float m[4], l[4];
    float4 o[4][4];
    #pragma unroll
    for (int i = 0; i < 4; i++) {
        m[i] = -3.0e38f; l[i] = 0.f;
        #pragma unroll
        for (int j = 0; j < 4; j++) o[i][j] = make_float4(0.f, 0.f, 0.f, 0.f);
    }
    __syncthreads();

    for (int kt = 0; kt <= qb; kt++) {
        const float4* Kg = (const float4*)(K + ((size_t)b * SSZ + kt * 64) * HSZ);
        const float4* Vg = (const float4*)(V + ((size_t)b * SSZ + kt * 64) * HSZ);
        for (int idx = tid; idx < 4096; idx += 256) {
            Kt[(idx & 63) * 65 + (idx >> 6)] = Kg[idx];
            Vs[idx] = Vg[idx];
        }
        __syncthreads();

        float s[4][4];
        #pragma unroll
        for (int i = 0; i < 4; i++)
            #pragma unroll
            for (int j = 0; j < 4; j++) s[i][j] = 0.f;

        #pragma unroll 4
        for (int d4 = 0; d4 < 64; d4++) {
            float4 qa[4], kb[4];
            #pragma unroll
            for (int i = 0; i < 4; i++) qa[i] = Qt[d4 * 65 + qf + 16 * i];
            #pragma unroll
            for (int j = 0; j < 4; j++) kb[j] = Kt[d4 * 65 + kf + 16 * j];
            #pragma unroll
            for (int i = 0; i < 4; i++)
                #pragma unroll
                for (int j = 0; j < 4; j++) {
                    s[i][j] = fmaf(qa[i].x, kb[j].x, s[i][j]);
                    s[i][j] = fmaf(qa[i].y, kb[j].y, s[i][j]);
                    s[i][j] = fmaf(qa[i].z, kb[j].z, s[i][j]);
                    s[i][j] = fmaf(qa[i].w, kb[j].w, s[i][j]);
                }
        }
        if (kt == qb) {
            #pragma unroll
            for (int i = 0; i < 4; i++)
                #pragma unroll
                for (int j = 0; j < 4; j++)
                    if (kf + 16 * j > qf + 16 * i) s[i][j] = -3.0e38f;
        }
        #pragma unroll
        for (int i = 0; i < 4; i++) {
            float tm = fmaxf(fmaxf(s[i][0], s[i][1]), fmaxf(s[i][2], s[i][3]));
            tm = hmax16(tm);
            float mn = fmaxf(m[i], tm);
            float alpha = __expf(m[i] - mn);
            m[i] = mn;
            float rs = 0.f;
            #pragma unroll
            for (int j = 0; j < 4; j++) {
                float pv = __expf(s[i][j] - mn);
                rs += pv;
                Ps[(qf + 16 * i) * 65 + kf + 16 * j] = pv;
            }
            rs = hsum16(rs);
            l[i] = l[i] * alpha + rs;
            #pragma unroll
            for (int j = 0; j < 4; j++) {
                o[i][j].x *= alpha; o[i][j].y *= alpha;
                o[i][j].z *= alpha; o[i][j].w *= alpha;
            }
        }
        __syncthreads();

        #pragma unroll 4
        for (int k = 0; k < 64; k++) {
            float pv[4];
            float4 vv[4];
            #pragma unroll
            for (int i = 0; i < 4; i++) pv[i] = Ps[(qf + 16 * i) * 65 + k];
            #pragma unroll
            for (int j = 0; j < 4; j++) vv[j] = Vs[k * 64 + kf + 16 * j];
            #pragma unroll
            for (int i = 0; i < 4; i++)
                #pragma unroll
                for (int j = 0; j < 4; j++) {
                    o[i][j].x = fmaf(pv[i], vv[j].x, o[i][j].x);
                    o[i][j].y = fmaf(pv[i], vv[j].y, o[i][j].y);
                    o[i][j].z = fmaf(pv[i], vv[j].z, o[i][j].z);
                    o[i][j].w = fmaf(pv[i], vv[j].w, o[i][j].w);
                }
        }
        __syncthreads();
    }

    float4* Og = (float4*)(O + ((size_t)b * SSZ + qb * 64) * HSZ);
    #pragma unroll
    for (int i = 0; i < 4; i++) {
        float inv = 1.f / l[i];
        #pragma unroll
        for (int j = 0; j < 4; j++) {
            float4 w = o[i][j];
            w.x *= inv; w.y *= inv; w.z *= inv; w.w *= inv;
            Og[(qf + 16 * i) * 64 + kf + 16 * j] = w;
        }
    }
}

// ---------------------------------------------------------------------------
extern "C" void kernel_launch(void* const* d_in, const int* in_sizes, int n_in,
                              void* d_out, int out_size)
{
    const float* x    = (const float*)d_in[0];
    const int*   lens = (const int*)  d_in[1];
    const float* w_ih = (const float*)d_in[2];
    const float* w_hh = (const float*)d_in[3];
    const float* b_ih = (const float*)d_in[4];
    const float* b_hh = (const float*)d_in[5];
    const float* Wq   = (const float*)d_in[6];
    const float* bq   = (const float*)d_in[7];
    const float* Wk   = (const float*)d_in[8];
    const float* bk   = (const float*)d_in[9];
    const float* Wv   = (const float*)d_in[10];
    const float* bv   = (const float*)d_in[11];
    const float* Wp   = (const float*)d_in[12];
    const float* bp   = (const float*)d_in[13];
    float* out = (float*)d_out;

    float *xg, *b0, *b1, *q, *k, *v;
    cudaGetSymbolAddress((void**)&xg, g_xg);
    cudaGetSymbolAddress((void**)&b0, g_b0);
    cudaGetSymbolAddress((void**)&b1, g_b1);
    cudaGetSymbolAddress((void**)&q,  g_q);
    cudaGetSymbolAddress((void**)&k,  g_k);
    cudaGetSymbolAddress((void**)&v,  g_v);

    cudaFuncSetAttribute(attn_kernel, cudaFuncAttributeMaxDynamicSharedMemorySize, ATTN_SMEM_BYTES);

    const int M = BSZ * SSZ;

    // pre-gates: xg = x @ w_ih^T + (b_ih + b_hh)        [launch 1]
    gemm_tn<<<dim3(G4H / 64, M / 64), 256>>>(x, w_ih, b_ih, b_hh, nullptr,
                                             xg, M, G4H, 64);
    nop_a<<<1, 32>>>();                                // [launch 2]
    nop_a<<<1, 32>>>();                                // [launch 3]
    // LSTM (runs its recurrence 2x internally; output identical)
    // MEASUREMENT: L = T_this_round - 3389us.
    lstm_kernel<<<128, 256>>>(xg, w_hh, lens, b0);     // [launch 4 == ncu slot]

    float* cur = b0;
    float* nxt = b1;
    for (int layer = 0; layer < 2; layer++) {
        const float* wql = Wq + (size_t)layer * HSZ * HSZ;
        const float* wkl = Wk + (size_t)layer * HSZ * HSZ;
        const float* wvl = Wv + (size_t)layer * HSZ * HSZ;
        gemm_tn<<<dim3(HSZ / 64, M / 64), 256>>>(cur, wql, bq + layer * HSZ, nullptr, nullptr, q, M, HSZ, HSZ);
        gemm_tn<<<dim3(HSZ / 64, M / 64), 256>>>(cur, wkl, bk + layer * HSZ, nullptr, nullptr, k, M, HSZ, HSZ);
        gemm_tn<<<dim3(HSZ / 64, M / 64), 256>>>(cur, wvl, bv + layer * HSZ, nullptr, nullptr, v, M, HSZ, HSZ);
        attn_kernel<<<dim3(16, 16), 256, ATTN_SMEM_BYTES>>>(q, k, v, nxt);
        float* tmp = cur; cur = nxt; nxt = tmp;
    }

    // output projection with validity mask
    gemm_tn<<<dim3(1, M / 64), 256>>>(cur, Wp, bp, nullptr, lens, out, M, 64, HSZ);
}

// round 16
// speedup vs baseline: 1.6547x; 1.6547x over previous
#include <cuda_runtime.h>
#include <math.h>

#define BSZ 16
#define SSZ 1024
#define HSZ 256
#define G4H 1024

// ------------------------- scratch (__device__ globals) ---------------------
__device__ float g_xg[BSZ * SSZ * G4H];
__device__ float g_b0[BSZ * SSZ * HSZ];
__device__ float g_b1[BSZ * SSZ * HSZ];
__device__ float g_q [BSZ * SSZ * HSZ];
__device__ float g_k [BSZ * SSZ * HSZ];
__device__ float g_v [BSZ * SSZ * HSZ];

__global__ void nop_a() {}

// ---------------------------------------------------------------------------
// fp32 GEMM (kept for xg: feeds the LSTM recurrence, keep full precision).
// C[M,N] = A[M,K] @ Bm[N,K]^T + bias[N] (+bias2[N]), optional row mask.
// ---------------------------------------------------------------------------
__global__ __launch_bounds__(256) void gemm_tn(
    const float* __restrict__ A, const float* __restrict__ Bm,
    const float* __restrict__ bias, const float* __restrict__ bias2,
    const int* __restrict__ lengths,
    float* __restrict__ C, int M, int N, int K)
{
    __shared__ float sA[16][68];
    __shared__ float sB[16][68];

    const int tid = threadIdx.x;
    const int tx = tid & 15;
    const int ty = tid >> 4;
    const int m0 = blockIdx.y * 64;
    const int n0 = blockIdx.x * 64;
    const int am = tid >> 2;
    const int ak = (tid & 3) * 4;

    float c[4][4];
    #pragma unroll
    for (int i = 0; i < 4; i++)
        #pragma unroll
        for (int j = 0; j < 4; j++) c[i][j] = 0.f;

    for (int k0 = 0; k0 < K; k0 += 16) {
        float4 av = *(const float4*)(A  + (size_t)(m0 + am) * K + k0 + ak);
        float4 bv = *(const float4*)(Bm + (size_t)(n0 + am) * K + k0 + ak);
        __syncthreads();
        sA[ak+0][am] = av.x; sA[ak+1][am] = av.y; sA[ak+2][am] = av.z; sA[ak+3][am] = av.w;
        sB[ak+0][am] = bv.x; sB[ak+1][am] = bv.y; sB[ak+2][am] = bv.z; sB[ak+3][am] = bv.w;
        __syncthreads();
        #pragma unroll
        for (int k = 0; k < 16; k++) {
            float4 a4 = *(const float4*)(&sA[k][ty << 2]);
            float4 b4 = *(const float4*)(&sB[k][tx << 2]);
            float ar[4] = {a4.x, a4.y, a4.z, a4.w};
            float br[4] = {b4.x, b4.y, b4.z, b4.w};
            #pragma unroll
            for (int i = 0; i < 4; i++)
                #pragma unroll
                for (int j = 0; j < 4; j++)
                    c[i][j] = fmaf(ar[i], br[j], c[i][j]);
        }
    }

    const int nn = n0 + (tx << 2);
    float bb[4];
    #pragma unroll
    for (int j = 0; j < 4; j++) {
        bb[j] = bias ? bias[nn + j] : 0.f;
        if (bias2) bb[j] += bias2[nn + j];
    }
    #pragma unroll
    for (int i = 0; i < 4; i++) {
        int rowm = m0 + (ty << 2) + i;
        float msk = 1.f;
        if (lengths) {
            int bt = rowm >> 10;
            int sq = rowm & 1023;
            msk = (sq < lengths[bt]) ? 1.f : 0.f;
        }
        float4 o;
        o.x = (c[i][0] + bb[0]) * msk;
        o.y = (c[i][1] + bb[1]) * msk;
        o.z = (c[i][2] + bb[2]) * msk;
        o.w = (c[i][3] + bb[3]) * msk;
        *(float4*)(C + (size_t)rowm * N + nn) = o;
    }
}

// ---------------------------------------------------------------------------
// tf32 tensor-core GEMM (mma.sync.m16n8k8), same TN contract + bias + mask.
// Block 64x64x16, 8 warps: warp w -> m-block (w&3), n-half (w>>2) = 16x32.
// Fragment loads from the k-major smem staging (sA[k][m], sB[k][n]) are
// conflict-free. cvt.rna rounding; fp32 accumulate.
// ---------------------------------------------------------------------------
__device__ __forceinline__ unsigned cvt_tf32(float x) {
    unsigned u;
    asm("cvt.rna.tf32.f32 %0, %1;" : "=r"(u) : "f"(x));
    return u;
}
__device__ __forceinline__ void mma_tf32(float* d,
    unsigned a0, unsigned a1, unsigned a2, unsigned a3,
    unsigned b0, unsigned b1)
{
    asm volatile(
        "mma.sync.aligned.m16n8k8.row.col.f32.tf32.tf32.f32 "
        "{%0,%1,%2,%3}, {%4,%5,%6,%7}, {%8,%9}, {%0,%1,%2,%3};"
        : "+f"(d[0]), "+f"(d[1]), "+f"(d[2]), "+f"(d[3])
        : "r"(a0), "r"(a1), "r"(a2), "r"(a3), "r"(b0), "r"(b1));
}

__global__ __launch_bounds__(256) void gemm_tn_tf32(
    const float* __restrict__ A, const float* __restrict__ Bm,
    const float* __restrict__ bias, const int* __restrict__ lengths,
    float* __restrict__ C, int M, int N, int K)
{
    __shared__ float sA[16][68];
    __shared__ float sB[16][68];

    const int tid  = threadIdx.x;
    const int lane = tid & 31;
    const int w    = tid >> 5;
    const int mb   = w & 3;          // m-block (16 rows)
    const int nh   = w >> 1 & 0xfffffffe; // unused; keep simple below
    const int nhalf = w >> 2;        // n-half (32 cols)
    const int m0 = blockIdx.y * 64;
    const int n0 = blockIdx.x * 64;
    const int am = tid >> 2;
    const int ak = (tid & 3) * 4;
    const int lr = lane >> 2;        // 0..7
    const int lc = lane & 3;         // 0..3
    const int moff = mb * 16;
    const int noff = nhalf * 32;
    (void)nh;

    float acc[4][4];
    #pragma unroll
    for (int i = 0; i < 4; i++)
        #pragma unroll
        for (int j = 0; j < 4; j++) acc[i][j] = 0.f;

    for (int k0 = 0; k0 < K; k0 += 16) {
        float4 av = *(const float4*)(A  + (size_t)(m0 + am) * K + k0 + ak);
        float4 bv = *(const float4*)(Bm + (size_t)(n0 + am) * K + k0 + ak);
        __syncthreads();
        sA[ak+0][am] = av.x; sA[ak+1][am] = av.y; sA[ak+2][am] = av.z; sA[ak+3][am] = av.w;
        sB[ak+0][am] = bv.x; sB[ak+1][am] = bv.y; sB[ak+2][am] = bv.z; sB[ak+3][am] = bv.w;
        __syncthreads();
        #pragma unroll
        for (int kk = 0; kk < 16; kk += 8) {
            unsigned a0 = cvt_tf32(sA[kk + lc    ][moff + lr    ]);
            unsigned a1 = cvt_tf32(sA[kk + lc    ][moff + lr + 8]);
            unsigned a2 = cvt_tf32(sA[kk + lc + 4][moff + lr    ]);
            unsigned a3 = cvt_tf32(sA[kk + lc + 4][moff + lr + 8]);
            #pragma unroll
            for (int nb = 0; nb < 4; nb++) {
                unsigned b0 = cvt_tf32(sB[kk + lc    ][noff + nb * 8 + lr]);
                unsigned b1 = cvt_tf32(sB[kk + lc + 4][noff + nb * 8 + lr]);
                mma_tf32(acc[nb], a0, a1, a2, a3, b0, b1);
            }
        }
    }

    // epilogue: d frag rows (lr, lr+8), cols lc*2, lc*2+1 within each n8-block
    #pragma unroll
    for (int nb = 0; nb < 4; nb++) {
        int col = n0 + noff + nb * 8 + lc * 2;
        float bb0 = bias ? bias[col]     : 0.f;
        float bb1 = bias ? bias[col + 1] : 0.f;
        int r0 = m0 + moff + lr;
        int r1 = r0 + 8;
        float m0k = 1.f, m1k = 1.f;
        if (lengths) {
            m0k = ((r0 & 1023) < lengths[r0 >> 10]) ? 1.f : 0.f;
            m1k = ((r1 & 1023) < lengths[r1 >> 10]) ? 1.f : 0.f;
        }
        float2 v0 = make_float2((acc[nb][0] + bb0) * m0k, (acc[nb][1] + bb1) * m0k);
        float2 v1 = make_float2((acc[nb][2] + bb0) * m1k, (acc[nb][3] + bb1) * m1k);
        *(float2*)(C + (size_t)r0 * N + col) = v0;
        *(float2*)(C + (size_t)r1 * N + col) = v1;
    }
}

// ---------------------------------------------------------------------------
// LSTM recurrence (Round-12 configuration, single pass — measured 2011us).
// ---------------------------------------------------------------------------
__device__ __forceinline__ unsigned smem_u32(const void* p) {
    return (unsigned)__cvta_generic_to_shared(p);
}
__device__ __forceinline__ void cluster_sync_() {
    asm volatile("barrier.cluster.arrive.aligned;\n\tbarrier.cluster.wait.aligned;" ::: "memory");
}
__device__ __forceinline__ unsigned mapa_(unsigned laddr, int r) {
    unsigned ra;
    asm volatile("mapa.shared::cluster.u32 %0, %1, %2;" : "=r"(ra) : "r"(laddr), "r"(r));
    return ra;
}
__device__ __forceinline__ float sig_f(float x) {
    return __fdividef(1.f, 1.f + __expf(-x));
}
__device__ __forceinline__ float tanh_f(float x) {
    return 1.f - __fdividef(2.f, __expf(2.f * x) + 1.f);
}

__global__ __cluster_dims__(8, 1, 1) __launch_bounds__(256, 1)
void lstm_kernel(const float* __restrict__ xg, const float* __restrict__ w_hh,
                 const int* __restrict__ lengths, float* __restrict__ hout)
{
    __shared__ float4 wsm[8][256];
    __shared__ __align__(16) float h_s[2][256];
    __shared__ float sg[128];
    __shared__ __align__(8) unsigned long long mbar[2];

    unsigned rank;
    asm("mov.u32 %0, %%cluster_ctarank;" : "=r"(rank));
    const int batch = blockIdx.x >> 3;
    const int t  = threadIdx.x;
    const int g  = t >> 1;
    const int hh = t & 1;
    const int row = ((g >> 5) << 8) + (int)rank * 32 + (g & 31);
    const float4* wr = (const float4*)(w_hh + (size_t)row * 256 + hh * 128);

    float4 w[24];
    #pragma unroll
    for (int i = 0; i < 24; i++) w[i] = wr[i];
    #pragma unroll
    for (int j = 0; j < 8; j++) wsm[j][t] = wr[24 + j];

    h_s[0][t] = 0.f;
    h_s[1][t] = 0.f;
    if (t == 0) {
        asm volatile("mbarrier.init.shared.b64 [%0], 1;" :: "r"(smem_u32(&mbar[0])) : "memory");
        asm volatile("mbarrier.init.shared.b64 [%0], 1;" :: "r"(smem_u32(&mbar[1])) : "memory");
    }
    __syncthreads();
    cluster_sync_();

    unsigned ra0[2] = {0, 0}, ra1[2] = {0, 0}, rm0[2] = {0, 0}, rm1[2] = {0, 0};
    if (t < 32) {
        #pragma unroll
        for (int rep = 0; rep < 2; rep++) {
            int a = rep * 32 + t;
            int dst = a >> 3;
            int ch  = a & 7;
            ra0[rep] = mapa_(smem_u32(&h_s[0][(int)rank * 32 + ch * 4]), dst);
            ra1[rep] = mapa_(smem_u32(&h_s[1][(int)rank * 32 + ch * 4]), dst);
            rm0[rep] = mapa_(smem_u32(&mbar[0]), dst);
            rm1[rep] = mapa_(smem_u32(&mbar[1]), dst);
        }
    }

    const int len = lengths[batch];
    float c = 0.f;
    const float* xgb = xg + (size_t)batch * SSZ * G4H;
    float* hob = hout + (size_t)batch * SSZ * HSZ;
    float xgv = (hh == 0) ? __ldg(xgb + row) : 0.f;

    for (int s = 0; s < SSZ; s++) {
        float xgn = 0.f;
        if (hh == 0 && s < SSZ - 1) xgn = __ldg(xgb + (size_t)(s + 1) * G4H + row);

        if (t == 0 && s < SSZ - 1) {
            unsigned mb = smem_u32(&mbar[(s + 1) & 1]);
            asm volatile("mbarrier.arrive.expect_tx.shared.b64 _, [%0], %1;"
                         :: "r"(mb), "r"(1024u) : "memory");
        }

        if (s > 0) {
            unsigned ad = smem_u32(&mbar[s & 1]);
            unsigned par = (s & 1) ? ((unsigned)(s >> 1) & 1u)
                                   : (((unsigned)(s >> 1) + 1u) & 1u);
            asm volatile(
                "{\n\t.reg .pred P;\n"
                "WAITL%=:\n\t"
                "mbarrier.try_wait.parity.acquire.cta.shared::cta.b64 P, [%0], %1, 0x989680;\n\t"
                "@!P bra WAITL%=;\n\t}"
                :: "r"(ad), "r"(par) : "memory");
        }

        const float4* hp = (const float4*)(&h_s[s & 1][hh * 128]);
        float a0 = 0.f, a1 = 0.f, a2 = 0.f, a3 = 0.f;
        #pragma unroll
        for (int i = 0; i < 24; i++) {
            float4 hv = hp[i];
            a0 = fmaf(w[i].x, hv.x, a0);
            a1 = fmaf(w[i].y, hv.y, a1);
            a2 = fmaf(w[i].z, hv.z, a2);
            a3 = fmaf(w[i].w, hv.w, a3);
        }
        #pragma unroll
        for (int j = 0; j < 8; j++) {
            float4 wv = wsm[j][t];
            float4 hv = hp[24 + j];
            a0 = fmaf(wv.x, hv.x, a0);
            a1 = fmaf(wv.y, hv.y, a1);
            a2 = fmaf(wv.z, hv.z, a2);
            a3 = fmaf(wv.w, hv.w, a3);
        }
        float acc = (a0 + a1) + (a2 + a3);
        acc += __shfl_xor_sync(0xffffffffu, acc, 1);
        if (hh == 0) sg[g] = acc + xgv;
        __syncthreads();

        if (t < 32) {
            float gi = sig_f(sg[t]);
            float gf = sig_f(sg[32 + t]);
            float go = sig_f(sg[96 + t]);
            float tg = tanh_f(sg[64 + t]);
            c = gf * c + gi * tg;
            float hn = go * tanh_f(c);

            if (s < SSZ - 1) {
                const int np = (s + 1) & 1;
                #pragma unroll
                for (int rep = 0; rep < 2; rep++) {
                    int a  = rep * 32 + t;
                    int ch = a & 7;
                    unsigned ra = np ? ra1[rep] : ra0[rep];
                    unsigned rm = np ? rm1[rep] : rm0[rep];
                    unsigned vx = __float_as_uint(__shfl_sync(0xffffffffu, hn, ch * 4 + 0));
                    unsigned vy = __float_as_uint(__shfl_sync(0xffffffffu, hn, ch * 4 + 1));
                    unsigned vz = __float_as_uint(__shfl_sync(0xffffffffu, hn, ch * 4 + 2));
                    unsigned vw = __float_as_uint(__shfl_sync(0xffffffffu, hn, ch * 4 + 3));
                    asm volatile(
                        "st.async.shared::cluster.mbarrier::complete_tx::bytes.v4.b32 "
                        "[%0], {%1,%2,%3,%4}, [%5];"
                        :: "r"(ra), "r"(vx), "r"(vy), "r"(vz), "r"(vw), "r"(rm)
                        : "memory");
                }
            }
            hob[(size_t)s * HSZ + (int)rank * 32 + t] = (s < len) ? hn : 0.f;
        }
        xgv = xgn;
    }
    cluster_sync_();
}

// ---------------------------------------------------------------------------
// Flash-style causal attention, fp32, Dh=256. BQ=BK=64, 256 threads.
// ---------------------------------------------------------------------------
#define ATTN_SMEM_BYTES ((4160 + 4160 + 4096) * 16 + 4160 * 4)  // 215296 B

__device__ __forceinline__ float hmax16(float v) {
    v = fmaxf(v, __shfl_xor_sync(0xffffffffu, v, 8));
    v = fmaxf(v, __shfl_xor_sync(0xffffffffu, v, 4));
    v = fmaxf(v, __shfl_xor_sync(0xffffffffu, v, 2));
    v = fmaxf(v, __shfl_xor_sync(0xffffffffu, v, 1));
    return v;
}
__device__ __forceinline__ float hsum16(float v) {
    v += __shfl_xor_sync(0xffffffffu, v, 8);
    v += __shfl_xor_sync(0xffffffffu, v, 4);
    v += __shfl_xor_sync(0xffffffffu, v, 2);
    v += __shfl_xor_sync(0xffffffffu, v, 1);
    return v;
}

__global__ __launch_bounds__(256) void attn_kernel(
    const float* __restrict__ Q, const float* __restrict__ K,
    const float* __restrict__ V, float* __restrict__ O)
{
    extern __shared__ float smf[];
    float4* Qt = (float4*)smf;
    float4* Kt = Qt + 4160;
    float4* Vs = Kt + 4160;
    float*  Ps = (float*)(Vs + 4096);

    const int b   = blockIdx.y;
    const int qb  = (int)gridDim.x - 1 - (int)blockIdx.x;
    const int tid = threadIdx.x;
    const int kf  = tid & 15;
    const int qf  = tid >> 4;

    const float4* Qg = (const float4*)(Q + ((size_t)b * SSZ + qb * 64) * HSZ);
    for (int idx = tid; idx < 4096; idx += 256)
        Qt[(idx & 63) * 65 + (idx >> 6)] = Qg[idx];

    float m[4], l[4];
    float4 o[4][4];
    #pragma unroll
    for (int i = 0; i < 4; i++) {
        m[i] = -3.0e38f; l[i] = 0.f;
        #pragma unroll
        for (int j = 0; j < 4; j++) o[i][j] = make_float4(0.f, 0.f, 0.f, 0.f);
    }
    __syncthreads();

    for (int kt = 0; kt <= qb; kt++) {
        const float4* Kg = (const float4*)(K + ((size_t)b * SSZ + kt * 64) * HSZ);
        const float4* Vg = (const float4*)(V + ((size_t)b * SSZ + kt * 64) * HSZ);
        for (int idx = tid; idx < 4096; idx += 256) {
            Kt[(idx & 63) * 65 + (idx >> 6)] = Kg[idx];
            Vs[idx] = Vg[idx];
        }
        __syncthreads();

        float s[4][4];
        #pragma unroll
        for (int i = 0; i < 4; i++)
            #pragma unroll
            for (int j = 0; j < 4; j++) s[i][j] = 0.f;

        #pragma unroll 4
        for (int d4 = 0; d4 < 64; d4++) {
            float4 qa[4], kb[4];
            #pragma unroll
            for (int i = 0; i < 4; i++) qa[i] = Qt[d4 * 65 + qf + 16 * i];
            #pragma unroll
            for (int j = 0; j < 4; j++) kb[j] = Kt[d4 * 65 + kf + 16 * j];
            #pragma unroll
            for (int i = 0; i < 4; i++)
                #pragma unroll
                for (int j = 0; j < 4; j++) {
                    s[i][j] = fmaf(qa[i].x, kb[j].x, s[i][j]);
                    s[i][j] = fmaf(qa[i].y, kb[j].y, s[i][j]);
                    s[i][j] = fmaf(qa[i].z, kb[j].z, s[i][j]);
                    s[i][j] = fmaf(qa[i].w, kb[j].w, s[i][j]);
                }
        }
        if (kt == qb) {
            #pragma unroll
            for (int i = 0; i < 4; i++)
                #pragma unroll
                for (int j = 0; j < 4; j++)
                    if (kf + 16 * j > qf + 16 * i) s[i][j] = -3.0e38f;
        }
        #pragma unroll
        for (int i = 0; i < 4; i++) {
            float tm = fmaxf(fmaxf(s[i][0], s[i][1]), fmaxf(s[i][2], s[i][3]));
            tm = hmax16(tm);
            float mn = fmaxf(m[i], tm);
            float alpha = __expf(m[i] - mn);
            m[i] = mn;
            float rs = 0.f;
            #pragma unroll
            for (int j = 0; j < 4; j++) {
                float pv = __expf(s[i][j] - mn);
                rs += pv;
                Ps[(qf + 16 * i) * 65 + kf + 16 * j] = pv;
            }
            rs = hsum16(rs);
            l[i] = l[i] * alpha + rs;
            #pragma unroll
            for (int j = 0; j < 4; j++) {
                o[i][j].x *= alpha; o[i][j].y *= alpha;
                o[i][j].z *= alpha; o[i][j].w *= alpha;
            }
        }
        __syncthreads();

        #pragma unroll 4
        for (int k = 0; k < 64; k++) {
            float pv[4];
            float4 vv[4];
            #pragma unroll
            for (int i = 0; i < 4; i++) pv[i] = Ps[(qf + 16 * i) * 65 + k];
            #pragma unroll
            for (int j = 0; j < 4; j++) vv[j] = Vs[k * 64 + kf + 16 * j];
            #pragma unroll
            for (int i = 0; i < 4; i++)
                #pragma unroll
                for (int j = 0; j < 4; j++) {
                    o[i][j].x = fmaf(pv[i], vv[j].x, o[i][j].x);
                    o[i][j].y = fmaf(pv[i], vv[j].y, o[i][j].y);
                    o[i][j].z = fmaf(pv[i], vv[j].z, o[i][j].z);
                    o[i][j].w = fmaf(pv[i], vv[j].w, o[i][j].w);
                }
        }
        __syncthreads();
    }

    float4* Og = (float4*)(O + ((size_t)b * SSZ + qb * 64) * HSZ);
    #pragma unroll
    for (int i = 0; i < 4; i++) {
        float inv = 1.f / l[i];
        #pragma unroll
        for (int j = 0; j < 4; j++) {
            float4 w = o[i][j];
            w.x *= inv; w.y *= inv; w.z *= inv; w.w *= inv;
            Og[(qf + 16 * i) * 64 + kf + 16 * j] = w;
        }
    }
}

// ---------------------------------------------------------------------------
extern "C" void kernel_launch(void* const* d_in, const int* in_sizes, int n_in,
                              void* d_out, int out_size)
{
    const float* x    = (const float*)d_in[0];
    const int*   lens = (const int*)  d_in[1];
    const float* w_ih = (const float*)d_in[2];
    const float* w_hh = (const float*)d_in[3];
    const float* b_ih = (const float*)d_in[4];
    const float* b_hh = (const float*)d_in[5];
    const float* Wq   = (const float*)d_in[6];
    const float* bq   = (const float*)d_in[7];
    const float* Wk   = (const float*)d_in[8];
    const float* bk   = (const float*)d_in[9];
    const float* Wv   = (const float*)d_in[10];
    const float* bv   = (const float*)d_in[11];
    const float* Wp   = (const float*)d_in[12];
    const float* bp   = (const float*)d_in[13];
    float* out = (float*)d_out;

    float *xg, *b0, *b1, *q, *k, *v;
    cudaGetSymbolAddress((void**)&xg, g_xg);
    cudaGetSymbolAddress((void**)&b0, g_b0);
    cudaGetSymbolAddress((void**)&b1, g_b1);
    cudaGetSymbolAddress((void**)&q,  g_q);
    cudaGetSymbolAddress((void**)&k,  g_k);
    cudaGetSymbolAddress((void**)&v,  g_v);

    cudaFuncSetAttribute(attn_kernel, cudaFuncAttributeMaxDynamicSharedMemorySize, ATTN_SMEM_BYTES);

    const int M = BSZ * SSZ;

    // pre-gates (fp32 — feeds the recurrence)            [launch 1]
    gemm_tn<<<dim3(G4H / 64, M / 64), 256>>>(x, w_ih, b_ih, b_hh, nullptr,
                                             xg, M, G4H, 64);
    // LSTM recurrence -> b0                              [launch 2]
    lstm_kernel<<<128, 256>>>(xg, w_hh, lens, b0);
    nop_a<<<1, 32>>>();                                 // [launch 3]

    float* cur = b0;
    float* nxt = b1;
    for (int layer = 0; layer < 2; layer++) {
        const float* wql = Wq + (size_t)layer * HSZ * HSZ;
        const float* wkl = Wk + (size_t)layer * HSZ * HSZ;
        const float* wvl = Wv + (size_t)layer * HSZ * HSZ;
        // [launch 4 == ncu slot on layer 0: first tf32 GEMM]
        gemm_tn_tf32<<<dim3(HSZ / 64, M / 64), 256>>>(cur, wql, bq + layer * HSZ, nullptr, q, M, HSZ, HSZ);
        gemm_tn_tf32<<<dim3(HSZ / 64, M / 64), 256>>>(cur, wkl, bk + layer * HSZ, nullptr, k, M, HSZ, HSZ);
        gemm_tn_tf32<<<dim3(HSZ / 64, M / 64), 256>>>(cur, wvl, bv + layer * HSZ, nullptr, v, M, HSZ, HSZ);
        attn_kernel<<<dim3(16, 16), 256, ATTN_SMEM_BYTES>>>(q, k, v, nxt);
        float* tmp = cur; cur = nxt; nxt = tmp;
    }

    // output projection (tf32) with validity mask
    gemm_tn_tf32<<<dim3(1, M / 64), 256>>>(cur, Wp, bp, lens, out, M, 64, HSZ);
}